// round 5
// baseline (speedup 1.0000x reference)
#include <cuda_runtime.h>
#include <cstdint>

#define HH 64
#define WW 64
#define HW 4096
#define CCH 256
#define NK 33

// Scratch
__device__ float g_G[2u * 256u * 4096u];  // G = Mt @ Ftε + u, per batch
__device__ float g_M[256u * 256u];        // Mt[d][c] = sum_o Wg[o,c] Wf[o,d]
__device__ float g_u[256u];               // u[d] = sum_o bg[o] Wf[o,d]

// ---------------------------------------------------------------------------
// f32x2 packed helpers (FFMA2 via PTX fma.rn.f32x2)
// ---------------------------------------------------------------------------
__device__ __forceinline__ unsigned long long pack2_bcast(float x) {
  unsigned long long r;
  asm("mov.b64 %0, {%1, %1};" : "=l"(r) : "f"(x));
  return r;
}
__device__ __forceinline__ unsigned long long ffma2(unsigned long long a,
                                                    unsigned long long b,
                                                    unsigned long long c) {
  unsigned long long d;
  asm("fma.rn.f32x2 %0, %1, %2, %3;" : "=l"(d) : "l"(a), "l"(b), "l"(c));
  return d;
}
__device__ __forceinline__ void unpack2(unsigned long long v, float& lo, float& hi) {
  asm("mov.b64 {%0, %1}, %2;" : "=f"(lo), "=f"(hi) : "l"(v));
}

// ---------------------------------------------------------------------------
// Kernel 0: prep.  Blocks 0..255: 16x16 tile of Mt.  Block 256: u.
// ---------------------------------------------------------------------------
__global__ __launch_bounds__(256) void psla_prep(const float* __restrict__ Wf,
                                                 const float* __restrict__ Wg,
                                                 const float* __restrict__ bg) {
  const int tid = threadIdx.x;
  if (blockIdx.x == 256) {
    // u[d] = sum_o bg[o] * Wf[o][d]
    float s = 0.f;
#pragma unroll 16
    for (int o = 0; o < 256; o++) s = fmaf(bg[o], Wf[o * 256 + tid], s);
    g_u[tid] = s;
    return;
  }
  __shared__ float sg[256][17], sf[256][17];
  const int c0 = (blockIdx.x & 15) * 16;
  const int d0 = (blockIdx.x >> 4) * 16;
  // thread tid loads row o = tid (16 floats from each matrix)
#pragma unroll
  for (int j = 0; j < 4; j++) {
    float4 a = *(const float4*)(Wg + (size_t)tid * 256 + c0 + 4 * j);
    float4 b = *(const float4*)(Wf + (size_t)tid * 256 + d0 + 4 * j);
    sg[tid][4 * j + 0] = a.x; sg[tid][4 * j + 1] = a.y;
    sg[tid][4 * j + 2] = a.z; sg[tid][4 * j + 3] = a.w;
    sf[tid][4 * j + 0] = b.x; sf[tid][4 * j + 1] = b.y;
    sf[tid][4 * j + 2] = b.z; sf[tid][4 * j + 3] = b.w;
  }
  __syncthreads();
  const int tc = tid & 15, td = tid >> 4;
  float m = 0.f;
#pragma unroll 8
  for (int o = 0; o < 256; o++) m = fmaf(sg[o][tc], sf[o][td], m);
  g_M[(size_t)(d0 + td) * 256 + (c0 + tc)] = m;
}

// ---------------------------------------------------------------------------
// Kernel 1: G = Mt (256x256) @ Ftε (256x4096) + u, per batch.
// 128x128 block tile, kc=8, 256 threads, 8x8 microtile, FFMA2 core.
// grid = (32 p-tiles, 2 o-tiles * 2 batches)
// ---------------------------------------------------------------------------
__global__ __launch_bounds__(256) void psla_gemm(const float* __restrict__ Fte) {
  __shared__ float sA[8][132];  // [k][d] (transposed Mt tile)
  __shared__ float sB[8][132];  // [k][p]

  const int b = blockIdx.y & 1;
  const int o0 = (blockIdx.y >> 1) * 128;
  const float* X = Fte + (size_t)b * CCH * HW;
  float* Go = g_G + (size_t)b * CCH * HW;

  const int p0 = blockIdx.x * 128;
  const int tid = threadIdx.x;
  const int tx = tid & 15, ty = tid >> 4;

  unsigned long long acc2[8][4];
#pragma unroll
  for (int i = 0; i < 8; i++)
#pragma unroll
    for (int j = 0; j < 4; j++) acc2[i][j] = 0ull;

  const int arow = tid >> 1, acg = (tid & 1) * 4;
  const int brow = tid >> 5, bcol = (tid & 31) * 4;

  for (int k0 = 0; k0 < CCH; k0 += 8) {
    float4 av = *(const float4*)(g_M + (size_t)(o0 + arow) * CCH + k0 + acg);
    float4 bv = *(const float4*)(X + (size_t)(k0 + brow) * HW + p0 + bcol);
    __syncthreads();
    sA[acg + 0][arow] = av.x;
    sA[acg + 1][arow] = av.y;
    sA[acg + 2][arow] = av.z;
    sA[acg + 3][arow] = av.w;
    *(float4*)&sB[brow][bcol] = bv;
    __syncthreads();
#pragma unroll
    for (int kk = 0; kk < 8; kk++) {
      float a[8];
      *(float4*)&a[0] = *(const float4*)&sA[kk][ty * 8];
      *(float4*)&a[4] = *(const float4*)&sA[kk][ty * 8 + 4];
      unsigned long long b2[4];
      ulonglong2 bl0 = *(const ulonglong2*)&sB[kk][tx * 8];
      ulonglong2 bl1 = *(const ulonglong2*)&sB[kk][tx * 8 + 4];
      b2[0] = bl0.x; b2[1] = bl0.y; b2[2] = bl1.x; b2[3] = bl1.y;
      unsigned long long a2[8];
#pragma unroll
      for (int i = 0; i < 8; i++) a2[i] = pack2_bcast(a[i]);
#pragma unroll
      for (int i = 0; i < 8; i++)
#pragma unroll
        for (int j = 0; j < 4; j++) acc2[i][j] = ffma2(a2[i], b2[j], acc2[i][j]);
    }
  }

#pragma unroll
  for (int i = 0; i < 8; i++) {
    const int o = o0 + ty * 8 + i;
    const float bvv = g_u[o];
    float r[8];
#pragma unroll
    for (int j = 0; j < 4; j++) unpack2(acc2[i][j], r[2 * j], r[2 * j + 1]);
#pragma unroll
    for (int j = 0; j < 8; j += 4) {
      float4 v;
      v.x = r[j + 0] + bvv;
      v.y = r[j + 1] + bvv;
      v.z = r[j + 2] + bvv;
      v.w = r[j + 3] + bvv;
      *(float4*)(Go + (size_t)o * HW + p0 + tx * 8 + j) = v;
    }
  }
}

// ---------------------------------------------------------------------------
// Kernel 2: sparse local attention, v4.
// Tile = 8(x) x 4(y) pixels, 256 threads = 32 px * 8 channel-subgroups of 4.
// Halo 16 x 12 = 192 sites. smem [2][192][36] = 55296 B -> 2 CTAs/SM.
// aff[k] = <G(p), Ft(p+delta_k)>; both phases stream the same Ft halo.
// ---------------------------------------------------------------------------
#define SST 36
#define NSITE 192
#define ABUF (NSITE * SST)

__device__ __forceinline__ void fetch6(const float* __restrict__ P, int base,
                                       int chbase, const bool* hin,
                                       const int* ha, float4* hv) {
#pragma unroll
  for (int t = 0; t < 6; t++) {
    const float* p0 = P + (size_t)(base + chbase) * HW + ha[t];
    float4 v;
    v.x = hin[t] ? p0[0] : 0.f;
    v.y = hin[t] ? p0[HW] : 0.f;
    v.z = hin[t] ? p0[2 * HW] : 0.f;
    v.w = hin[t] ? p0[3 * HW] : 0.f;
    hv[t] = v;
  }
}
__device__ __forceinline__ void store6(float* buf, int px, int chbase,
                                       const float4* hv) {
#pragma unroll
  for (int t = 0; t < 6; t++)
    *(float4*)(buf + (t * 32 + px) * SST + chbase) = hv[t];
}

__global__ __launch_bounds__(256, 2) void psla_attn(const float* __restrict__ Ft,
                                                    float* __restrict__ out) {
  extern __shared__ float sm[];
  constexpr int kdx[NK] = {0, -1,-1,-1,0,0,1,1,1, -2,-2,-2,0,0,2,2,2,
                           -3,-3,-3,0,0,3,3,3, -4,-4,-4,0,0,4,4,4};
  constexpr int kdy[NK] = {0, -1,0,1,-1,1,-1,0,1, -2,0,2,-2,2,-2,0,2,
                           -3,0,3,-3,3,-3,0,3, -4,0,4,-4,4,-4,0,4};

  const int b = blockIdx.z;
  const int gx0 = blockIdx.x * 8, gy0 = blockIdx.y * 4;
  const int tid = threadIdx.x;
  const int px = tid >> 3, sub = tid & 7;
  const int lx = px & 7, ly = px >> 3;  // ly in 0..3
  const int gx = gx0 + lx, gy = gy0 + ly;
  const int gp = gy * WW + gx;

  const float* Gb  = g_G + (size_t)b * CCH * HW;
  const float* Ftb = Ft + (size_t)b * CCH * HW;

  // Halo mapping: this thread owns sites s = t*32 + px (t=0..5), channels sub*4..+3.
  int ha[6];
  bool hin[6];
#pragma unroll
  for (int t = 0; t < 6; t++) {
    const int s = t * 32 + px;
    const int hy = gy0 - 4 + (s >> 4);
    const int hx = gx0 - 4 + (s & 15);
    hin[t] = ((unsigned)hy < HH) && ((unsigned)hx < WW);
    ha[t] = hy * WW + hx;
  }
  const int chbase = sub * 4;
  float* const mybuf0 = sm;  // store via store6(buf, px, chbase, ...)
  const float* const cbase = sm + ((ly + 4) * 16 + (lx + 4)) * SST + chbase;

  unsigned long long vmask = 0ull;
#pragma unroll
  for (int k = 0; k < NK; k++)
    if ((unsigned)(gy + kdx[k]) < HH && (unsigned)(gx + kdy[k]) < WW)
      vmask |= (1ull << k);

  float aff[NK];
#pragma unroll
  for (int k = 0; k < NK; k++) aff[k] = 0.f;

  float4 hn[6];
  float eg[4], egn[4];

  // ==== Phase A: aff[k] = <G(p), Ft(p+delta_k)> ====
  fetch6(Ftb, 0, chbase, hin, ha, hn);
#pragma unroll
  for (int cc = 0; cc < 4; cc++) eg[cc] = Gb[(size_t)(chbase + cc) * HW + gp];
  store6(mybuf0, px, chbase, hn);
  __syncthreads();

  for (int c0 = 0; c0 < 8; c0++) {
    if (c0 < 7) {
      const int base = (c0 + 1) * 32;
      fetch6(Ftb, base, chbase, hin, ha, hn);
#pragma unroll
      for (int cc = 0; cc < 4; cc++)
        egn[cc] = Gb[(size_t)(base + chbase + cc) * HW + gp];
    }
    const float* bp = cbase + (c0 & 1) * ABUF;
#pragma unroll
    for (int k = 0; k < NK; k++) {
      const float4 v = *(const float4*)(bp + (kdx[k] * 16 + kdy[k]) * SST);
      float s = fmaf(eg[0], v.x, 0.f);
      s = fmaf(eg[1], v.y, s);
      s = fmaf(eg[2], v.z, s);
      s = fmaf(eg[3], v.w, s);
      aff[k] += s;
    }
    if (c0 < 7) {
      store6(mybuf0 + ((c0 & 1) ^ 1) * ABUF, px, chbase, hn);
#pragma unroll
      for (int cc = 0; cc < 4; cc++) eg[cc] = egn[cc];
    }
    __syncthreads();
  }

  // Reduce partial dots across the 8 channel-subgroups (lanes xor 1,2,4).
#pragma unroll
  for (int k = 0; k < NK; k++) {
    aff[k] += __shfl_xor_sync(0xffffffffu, aff[k], 1);
    aff[k] += __shfl_xor_sync(0xffffffffu, aff[k], 2);
    aff[k] += __shfl_xor_sync(0xffffffffu, aff[k], 4);
  }

  // ==== Softmax over valid offsets (k=0 always valid) ====
  float m = aff[0];
#pragma unroll
  for (int k = 1; k < NK; k++)
    if ((vmask >> k) & 1ull) m = fmaxf(m, aff[k]);
  float ssum = 0.f;
#pragma unroll
  for (int k = 0; k < NK; k++) {
    if ((vmask >> k) & 1ull) {
      aff[k] = __expf(aff[k] - m);
      ssum += aff[k];
    } else {
      aff[k] = 0.f;
    }
  }
  const float inv = 1.f / ssum;
#pragma unroll
  for (int k = 0; k < NK; k++) aff[k] *= inv;

  // ==== Phase B: out(c,p) = sum_k w_k * Ft(c, p + delta_k) ====
  fetch6(Ftb, 0, chbase, hin, ha, hn);
  store6(mybuf0, px, chbase, hn);
  __syncthreads();

  for (int c0 = 0; c0 < 8; c0++) {
    if (c0 < 7) fetch6(Ftb, (c0 + 1) * 32, chbase, hin, ha, hn);

    const float* bp = cbase + (c0 & 1) * ABUF;
    float acc[4] = {0.f, 0.f, 0.f, 0.f};
#pragma unroll
    for (int k = 0; k < NK; k++) {
      const float4 v = *(const float4*)(bp + (kdx[k] * 16 + kdy[k]) * SST);
      const float wk = aff[k];
      acc[0] = fmaf(wk, v.x, acc[0]);
      acc[1] = fmaf(wk, v.y, acc[1]);
      acc[2] = fmaf(wk, v.z, acc[2]);
      acc[3] = fmaf(wk, v.w, acc[3]);
    }
#pragma unroll
    for (int cc = 0; cc < 4; cc++)
      out[(size_t)(b * CCH + c0 * 32 + chbase + cc) * HW + gp] = acc[cc];

    if (c0 < 7) store6(mybuf0 + ((c0 & 1) ^ 1) * ABUF, px, chbase, hn);
    __syncthreads();
  }
}

// ---------------------------------------------------------------------------
extern "C" void kernel_launch(void* const* d_in, const int* in_sizes, int n_in,
                              void* d_out, int out_size) {
  const float* Ft  = (const float*)d_in[0];
  const float* Fte = (const float*)d_in[1];
  const float* Wf  = (const float*)d_in[2];
  // d_in[3] = bf: provably cancels in the softmax (constant in k) — unused.
  const float* Wg  = (const float*)d_in[4];
  const float* bg  = (const float*)d_in[5];
  float* out = (float*)d_out;

  const int attn_smem = 2 * ABUF * (int)sizeof(float);  // 55296 B
  cudaFuncSetAttribute(psla_attn, cudaFuncAttributeMaxDynamicSharedMemorySize,
                       attn_smem);

  psla_prep<<<257, 256>>>(Wf, Wg, bg);

  dim3 gg(32, 4);  // p-tiles, (o-tile * 2 + batch)
  psla_gemm<<<gg, 256>>>(Fte);

  dim3 ga(8, 16, 2);  // W/8, H/4, B
  psla_attn<<<ga, 256, attn_smem>>>(Ft, out);
}

// round 6
// speedup vs baseline: 1.2400x; 1.2400x over previous
#include <cuda_runtime.h>
#include <cstdint>

#define HH 64
#define WW 64
#define HW 4096
#define CCH 256
#define NK 33

// Scratch
__device__ float g_G[2u * 256u * 4096u];  // G = Mt @ Fte + u, per batch
__device__ float g_M[256u * 256u];        // Mt[d][c] = sum_o Wg[o,c] Wf[o,d]
__device__ float g_u[256u];               // u[d]     = sum_o bg[o]   Wf[o,d]

// ---------------------------------------------------------------------------
// f32x2 packed helpers (FFMA2 via PTX fma.rn.f32x2)
// ---------------------------------------------------------------------------
__device__ __forceinline__ unsigned long long pack2_bcast(float x) {
  unsigned long long r;
  asm("mov.b64 %0, {%1, %1};" : "=l"(r) : "f"(x));
  return r;
}
__device__ __forceinline__ unsigned long long ffma2(unsigned long long a,
                                                    unsigned long long b,
                                                    unsigned long long c) {
  unsigned long long d;
  asm("fma.rn.f32x2 %0, %1, %2, %3;" : "=l"(d) : "l"(a), "l"(b), "l"(c));
  return d;
}
__device__ __forceinline__ void unpack2(unsigned long long v, float& lo, float& hi) {
  asm("mov.b64 {%0, %1}, %2;" : "=f"(lo), "=f"(hi) : "l"(v));
}

// ---------------------------------------------------------------------------
// Kernel 0: prep. Blocks 0..63: 32x32 tile of Mt (GEMM-style, kc=32, 2x2
// microtile). Block 64: u[d] = sum_o bg[o] Wf[o,d].
// ---------------------------------------------------------------------------
__global__ __launch_bounds__(256) void psla_prep(const float* __restrict__ Wf,
                                                 const float* __restrict__ Wg,
                                                 const float* __restrict__ bg) {
  const int tid = threadIdx.x;
  if (blockIdx.x == 64) {
    float s = 0.f;
#pragma unroll 8
    for (int o = 0; o < 256; o++) s = fmaf(bg[o], Wf[o * 256 + tid], s);
    g_u[tid] = s;
    return;
  }
  __shared__ float sg[32][33], sf[32][33];
  const int c0 = (blockIdx.x & 7) * 32;
  const int d0 = (blockIdx.x >> 3) * 32;
  const int lr = tid >> 3, lc = (tid & 7) * 4;
  const int tc = (tid & 15) * 2, td = (tid >> 4) * 2;

  float acc[2][2] = {{0.f, 0.f}, {0.f, 0.f}};
  for (int k0 = 0; k0 < 256; k0 += 32) {
    float4 a = *(const float4*)(Wg + (size_t)(k0 + lr) * 256 + c0 + lc);
    float4 b = *(const float4*)(Wf + (size_t)(k0 + lr) * 256 + d0 + lc);
    __syncthreads();
    sg[lr][lc + 0] = a.x; sg[lr][lc + 1] = a.y;
    sg[lr][lc + 2] = a.z; sg[lr][lc + 3] = a.w;
    sf[lr][lc + 0] = b.x; sf[lr][lc + 1] = b.y;
    sf[lr][lc + 2] = b.z; sf[lr][lc + 3] = b.w;
    __syncthreads();
#pragma unroll
    for (int kk = 0; kk < 32; kk++) {
      const float a0 = sg[kk][tc], a1 = sg[kk][tc + 1];
      const float b0 = sf[kk][td], b1 = sf[kk][td + 1];
      acc[0][0] = fmaf(a0, b0, acc[0][0]);
      acc[0][1] = fmaf(a1, b0, acc[0][1]);
      acc[1][0] = fmaf(a0, b1, acc[1][0]);
      acc[1][1] = fmaf(a1, b1, acc[1][1]);
    }
  }
#pragma unroll
  for (int i = 0; i < 2; i++)
#pragma unroll
    for (int j = 0; j < 2; j++)
      g_M[(size_t)(d0 + td + i) * 256 + (c0 + tc + j)] = acc[i][j];
}

// ---------------------------------------------------------------------------
// Kernel 1: G = Mt (256x256) @ Fte (256x4096) + u, per batch.
// 128x128 block tile, kc=8, 256 threads, 8x8 microtile, FFMA2 core.
// ---------------------------------------------------------------------------
__global__ __launch_bounds__(256) void psla_gemm(const float* __restrict__ Fte) {
  __shared__ float sA[8][132];
  __shared__ float sB[8][132];

  const int b = blockIdx.y & 1;
  const int o0 = (blockIdx.y >> 1) * 128;
  const float* X = Fte + (size_t)b * CCH * HW;
  float* Go = g_G + (size_t)b * CCH * HW;

  const int p0 = blockIdx.x * 128;
  const int tid = threadIdx.x;
  const int tx = tid & 15, ty = tid >> 4;

  unsigned long long acc2[8][4];
#pragma unroll
  for (int i = 0; i < 8; i++)
#pragma unroll
    for (int j = 0; j < 4; j++) acc2[i][j] = 0ull;

  const int arow = tid >> 1, acg = (tid & 1) * 4;
  const int brow = tid >> 5, bcol = (tid & 31) * 4;

  for (int k0 = 0; k0 < CCH; k0 += 8) {
    float4 av = *(const float4*)(g_M + (size_t)(o0 + arow) * CCH + k0 + acg);
    float4 bv = *(const float4*)(X + (size_t)(k0 + brow) * HW + p0 + bcol);
    __syncthreads();
    sA[acg + 0][arow] = av.x;
    sA[acg + 1][arow] = av.y;
    sA[acg + 2][arow] = av.z;
    sA[acg + 3][arow] = av.w;
    *(float4*)&sB[brow][bcol] = bv;
    __syncthreads();
#pragma unroll
    for (int kk = 0; kk < 8; kk++) {
      float a[8];
      *(float4*)&a[0] = *(const float4*)&sA[kk][ty * 8];
      *(float4*)&a[4] = *(const float4*)&sA[kk][ty * 8 + 4];
      unsigned long long b2[4];
      ulonglong2 bl0 = *(const ulonglong2*)&sB[kk][tx * 8];
      ulonglong2 bl1 = *(const ulonglong2*)&sB[kk][tx * 8 + 4];
      b2[0] = bl0.x; b2[1] = bl0.y; b2[2] = bl1.x; b2[3] = bl1.y;
      unsigned long long a2[8];
#pragma unroll
      for (int i = 0; i < 8; i++) a2[i] = pack2_bcast(a[i]);
#pragma unroll
      for (int i = 0; i < 8; i++)
#pragma unroll
        for (int j = 0; j < 4; j++) acc2[i][j] = ffma2(a2[i], b2[j], acc2[i][j]);
    }
  }

#pragma unroll
  for (int i = 0; i < 8; i++) {
    const int o = o0 + ty * 8 + i;
    const float bvv = g_u[o];
    float r[8];
#pragma unroll
    for (int j = 0; j < 4; j++) unpack2(acc2[i][j], r[2 * j], r[2 * j + 1]);
#pragma unroll
    for (int j = 0; j < 8; j += 4) {
      float4 v;
      v.x = r[j + 0] + bvv;
      v.y = r[j + 1] + bvv;
      v.z = r[j + 2] + bvv;
      v.w = r[j + 3] + bvv;
      *(float4*)(Go + (size_t)o * HW + p0 + tx * 8 + j) = v;
    }
  }
}

// ---------------------------------------------------------------------------
// Kernel 2: sparse local attention, v5.
// 8x8 pixel tile, 512 threads = 64 px * 8 subgroups of 4 channels.
// Triple-buffered smem halo [3][256 sites][36]; pipeline per chunk:
//   fetch(c+2) -> compute(c) -> store(c+1) -> sync.
// aff[k] = <G(p), Ft(p+delta_k)>; both phases stream the same Ft halo.
// ---------------------------------------------------------------------------
#define SST 36
#define ABUF (256 * SST)

__device__ __forceinline__ void halo_fetch(const float* __restrict__ P,
                                           int base, int cg0, bool hin,
                                           int haddr, float4* hv) {
#pragma unroll
  for (int j = 0; j < 4; j++) {
    const int c = base + (cg0 + 2 * j) * 4;
    float4 v;
    v.x = hin ? P[(size_t)(c + 0) * HW + haddr] : 0.f;
    v.y = hin ? P[(size_t)(c + 1) * HW + haddr] : 0.f;
    v.z = hin ? P[(size_t)(c + 2) * HW + haddr] : 0.f;
    v.w = hin ? P[(size_t)(c + 3) * HW + haddr] : 0.f;
    hv[j] = v;
  }
}
__device__ __forceinline__ void halo_store(float* bufq, int cg0,
                                           const float4* hv) {
#pragma unroll
  for (int j = 0; j < 4; j++)
    *(float4*)(bufq + (cg0 + 2 * j) * 4) = hv[j];
}

__global__ __launch_bounds__(512) void psla_attn(const float* __restrict__ Ft,
                                                 float* __restrict__ out) {
  extern __shared__ float sm[];
  constexpr int kdx[NK] = {0, -1,-1,-1,0,0,1,1,1, -2,-2,-2,0,0,2,2,2,
                           -3,-3,-3,0,0,3,3,3, -4,-4,-4,0,0,4,4,4};
  constexpr int kdy[NK] = {0, -1,0,1,-1,1,-1,0,1, -2,0,2,-2,2,-2,0,2,
                           -3,0,3,-3,3,-3,0,3, -4,0,4,-4,4,-4,0,4};

  const int b = blockIdx.z;
  const int gx0 = blockIdx.x * 8, gy0 = blockIdx.y * 8;
  const int tid = threadIdx.x;
  const int px = tid >> 3, sub = tid & 7;
  const int lx = px & 7, ly = px >> 3;
  const int gx = gx0 + lx, gy = gy0 + ly;
  const int gp = gy * WW + gx;

  const float* Gb  = g_G + (size_t)b * CCH * HW;
  const float* Ftb = Ft + (size_t)b * CCH * HW;

  const int q   = tid & 255;
  const int cg0 = tid >> 8;  // 0 or 1
  const int hy = gy0 - 4 + (q >> 4);
  const int hx = gx0 - 4 + (q & 15);
  const bool hin = ((unsigned)hy < HH) && ((unsigned)hx < WW);
  const int haddr = hy * WW + hx;
  float* const myq0 = sm + q * SST;

  const float* const cbase = sm + ((ly + 4) * 16 + (lx + 4)) * SST + sub * 4;

  unsigned long long vmask = 0ull;
#pragma unroll
  for (int k = 0; k < NK; k++)
    if ((unsigned)(gy + kdx[k]) < HH && (unsigned)(gx + kdy[k]) < WW)
      vmask |= (1ull << k);

  float aff[NK];
#pragma unroll
  for (int k = 0; k < NK; k++) aff[k] = 0.f;

  float4 h[2][4];
  float e[3][4];

  // ==== Phase A: aff[k] = <G(p), Ft(p+delta_k)> ====
  halo_fetch(Ftb, 0, cg0, hin, haddr, h[0]);
#pragma unroll
  for (int cc = 0; cc < 4; cc++) e[0][cc] = Gb[(size_t)(sub * 4 + cc) * HW + gp];
  halo_fetch(Ftb, 32, cg0, hin, haddr, h[1]);
#pragma unroll
  for (int cc = 0; cc < 4; cc++)
    e[1][cc] = Gb[(size_t)(32 + sub * 4 + cc) * HW + gp];
  halo_store(myq0, cg0, h[0]);  // buf 0 <- chunk 0
  __syncthreads();

#pragma unroll
  for (int c0 = 0; c0 < 8; c0++) {
    if (c0 < 6) {
      const int base = (c0 + 2) * 32;
      halo_fetch(Ftb, base, cg0, hin, haddr, h[c0 & 1]);
#pragma unroll
      for (int cc = 0; cc < 4; cc++)
        e[(c0 + 2) % 3][cc] = Gb[(size_t)(base + sub * 4 + cc) * HW + gp];
    }
    const float* bp = cbase + (c0 % 3) * ABUF;
    const float e0 = e[c0 % 3][0], e1 = e[c0 % 3][1];
    const float e2 = e[c0 % 3][2], e3 = e[c0 % 3][3];
#pragma unroll
    for (int k = 0; k < NK; k++) {
      const float4 v = *(const float4*)(bp + (kdx[k] * 16 + kdy[k]) * SST);
      float s = fmaf(e0, v.x, 0.f);
      s = fmaf(e1, v.y, s);
      s = fmaf(e2, v.z, s);
      s = fmaf(e3, v.w, s);
      aff[k] += s;
    }
    if (c0 < 7)
      halo_store(myq0 + ((c0 + 1) % 3) * ABUF, cg0, h[(c0 + 1) & 1]);
    __syncthreads();
  }

  // Reduce partial dots across the 8 channel-subgroups (lanes xor 1,2,4).
#pragma unroll
  for (int k = 0; k < NK; k++) {
    aff[k] += __shfl_xor_sync(0xffffffffu, aff[k], 1);
    aff[k] += __shfl_xor_sync(0xffffffffu, aff[k], 2);
    aff[k] += __shfl_xor_sync(0xffffffffu, aff[k], 4);
  }

  // ==== Softmax over valid offsets (k=0 always valid) ====
  float m = aff[0];
#pragma unroll
  for (int k = 1; k < NK; k++)
    if ((vmask >> k) & 1ull) m = fmaxf(m, aff[k]);
  float ssum = 0.f;
#pragma unroll
  for (int k = 0; k < NK; k++) {
    if ((vmask >> k) & 1ull) {
      aff[k] = __expf(aff[k] - m);
      ssum += aff[k];
    } else {
      aff[k] = 0.f;
    }
  }
  const float inv = 1.f / ssum;
#pragma unroll
  for (int k = 0; k < NK; k++) aff[k] *= inv;

  // ==== Phase B: out(c,p) = sum_k w_k * Ft(c, p + delta_k) ====
  halo_fetch(Ftb, 0, cg0, hin, haddr, h[0]);
  halo_fetch(Ftb, 32, cg0, hin, haddr, h[1]);
  halo_store(myq0, cg0, h[0]);
  __syncthreads();

#pragma unroll
  for (int c0 = 0; c0 < 8; c0++) {
    if (c0 < 6)
      halo_fetch(Ftb, (c0 + 2) * 32, cg0, hin, haddr, h[c0 & 1]);

    const float* bp = cbase + (c0 % 3) * ABUF;
    float acc[4] = {0.f, 0.f, 0.f, 0.f};
#pragma unroll
    for (int k = 0; k < NK; k++) {
      const float4 v = *(const float4*)(bp + (kdx[k] * 16 + kdy[k]) * SST);
      const float wk = aff[k];
      acc[0] = fmaf(wk, v.x, acc[0]);
      acc[1] = fmaf(wk, v.y, acc[1]);
      acc[2] = fmaf(wk, v.z, acc[2]);
      acc[3] = fmaf(wk, v.w, acc[3]);
    }
#pragma unroll
    for (int cc = 0; cc < 4; cc++)
      out[(size_t)(b * CCH + c0 * 32 + sub * 4 + cc) * HW + gp] = acc[cc];

    if (c0 < 7)
      halo_store(myq0 + ((c0 + 1) % 3) * ABUF, cg0, h[(c0 + 1) & 1]);
    __syncthreads();
  }
}

// ---------------------------------------------------------------------------
extern "C" void kernel_launch(void* const* d_in, const int* in_sizes, int n_in,
                              void* d_out, int out_size) {
  const float* Ft  = (const float*)d_in[0];
  const float* Fte = (const float*)d_in[1];
  const float* Wf  = (const float*)d_in[2];
  // d_in[3] = bf: cancels in the softmax (constant in k) — unused.
  const float* Wg  = (const float*)d_in[4];
  const float* bg  = (const float*)d_in[5];
  float* out = (float*)d_out;

  const int attn_smem = 3 * ABUF * (int)sizeof(float);  // 110592 B
  cudaFuncSetAttribute(psla_attn, cudaFuncAttributeMaxDynamicSharedMemorySize,
                       attn_smem);

  psla_prep<<<65, 256>>>(Wf, Wg, bg);

  dim3 gg(32, 4);  // p-tiles, (o-tile * 2 + batch)
  psla_gemm<<<gg, 256>>>(Fte);

  dim3 ga(8, 8, 2);  // W/8, H/8, B
  psla_attn<<<ga, 512, attn_smem>>>(Ft, out);
}